// round 8
// baseline (speedup 1.0000x reference)
#include <cuda_runtime.h>
#include <cstdint>
#include <math.h>

#define D_DIM   2048
#define E_DIM   64
#define TOPK    2
#define M_TILE  128
#define KC      32
#define NCHUNK  (D_DIM / KC)    /* 64 */
#define THREADS 128
#define STAGE   16384           /* one W stage: 64 experts x 256B (32k x 8B hi/lo) */
#define LG_STRIDE 65
#define SMEM_TOTAL 33536        /* max(2*STAGE, 128*65*4) rounded up; < 48KB */
#define TAU     1e-4f

__device__ __forceinline__ uint32_t smem_u32(const void* p) {
    uint32_t a;
    asm("{ .reg .u64 t; cvta.to.shared.u64 t, %1; cvt.u32.u64 %0, t; }" : "=r"(a) : "l"(p));
    return a;
}
__device__ __forceinline__ uint32_t f2tf32(float v) {
    uint32_t r;
    asm("cvt.rna.tf32.f32 %0, %1;" : "=r"(r) : "f"(v));
    return r;
}
__device__ __forceinline__ void mma_tf32(float* d, const uint32_t* a, uint32_t b0, uint32_t b1) {
    asm volatile(
        "mma.sync.aligned.m16n8k8.row.col.f32.tf32.tf32.f32 "
        "{%0,%1,%2,%3},{%4,%5,%6,%7},{%8,%9},{%0,%1,%2,%3};"
        : "+f"(d[0]), "+f"(d[1]), "+f"(d[2]), "+f"(d[3])
        : "r"(a[0]), "r"(a[1]), "r"(a[2]), "r"(a[3]), "r"(b0), "r"(b1));
}

extern __shared__ char smem[];

__global__ __launch_bounds__(THREADS, 1) void router_mma_kernel(
    const float* __restrict__ x, const float* __restrict__ W,
    float* __restrict__ out, int T)
{
    const uint32_t sb = smem_u32(smem);
    const int tid  = threadIdx.x;
    const int lane = tid & 31;
    const int wid  = tid >> 5;
    const int t0   = blockIdx.x * M_TILE;
    const int r    = lane >> 2;       // fragment row / expert-in-octet
    const int c    = lane & 3;        // fragment k index

    // ---- W loader mapping: thread -> (expert row, k half of 16) ----
    const int we = tid >> 1;
    const int wk = (tid & 1) * 16;
    const float* wp = W + (size_t)we * D_DIM + wk;

    // ---- A row pointers: warp owns rows wid*32 .. +31 ----
    const float* xr[4];
#pragma unroll
    for (int q = 0; q < 4; ++q)
        xr[q] = x + (size_t)(t0 + wid * 32 + q * 8 + r) * D_DIM;
    // q = mt*2 + row2: rows r, r+8 (mt0), r+16, r+24 (mt1)

    float acc[2][8][4];
#pragma unroll
    for (int mt = 0; mt < 2; ++mt)
#pragma unroll
        for (int nt = 0; nt < 8; ++nt)
#pragma unroll
            for (int d = 0; d < 4; ++d) acc[mt][nt][d] = 0.f;

    float4 wv[4];       // W chunk in flight (16 k-values for expert we)
    float  ar[2][32];   // A double buffer: [buf][mt*16 + g*4 + pos]

#define LOAD_W(kc)                                                            \
    {  _Pragma("unroll")                                                      \
       for (int j = 0; j < 4; ++j)                                            \
           wv[j] = *(const float4*)(wp + (kc) * KC + j * 4); }

#define STS_W(s)                                                              \
    {  _Pragma("unroll")                                                      \
       for (int j = 0; j < 4; ++j) {                                          \
           float vq[4] = {wv[j].x, wv[j].y, wv[j].z, wv[j].w};                \
           _Pragma("unroll")                                                  \
           for (int q = 0; q < 4; ++q) {                                      \
               int kl = wk + j * 4 + q;                                       \
               uint32_t hi = f2tf32(vq[q]);                                   \
               uint32_t lo = f2tf32(vq[q] - __uint_as_float(hi));             \
               int g = kl >> 3, m = kl & 7;                                   \
               uint32_t inner = (uint32_t)(g * 64 + (m & 3) * 16 + (m >> 2) * 8); \
               uint32_t addr = sb + (s) * STAGE + we * 256                    \
                             + (inner ^ (uint32_t)((we & 7) << 4));           \
               asm volatile("st.shared.v2.b32 [%0], {%1,%2};"                 \
                            :: "r"(addr), "r"(hi), "r"(lo) : "memory");       \
           } } }

#define LOAD_A(kc, b)                                                         \
    {  _Pragma("unroll")                                                      \
       for (int mt = 0; mt < 2; ++mt)                                         \
       _Pragma("unroll")                                                      \
       for (int g = 0; g < 4; ++g)                                            \
       _Pragma("unroll")                                                      \
       for (int pos = 0; pos < 4; ++pos)                                      \
           ar[b][mt * 16 + g * 4 + pos] =                                     \
               xr[mt * 2 + (pos & 1)][(kc) * KC + g * 8 + c + (pos >> 1) * 4]; }

#define COMPUTE(s, b)                                                         \
    {  _Pragma("unroll")                                                      \
       for (int g = 0; g < 4; ++g) {                                          \
           uint32_t ah[2][4], al[2][4];                                       \
           _Pragma("unroll")                                                  \
           for (int mt = 0; mt < 2; ++mt)                                     \
           _Pragma("unroll")                                                  \
           for (int pos = 0; pos < 4; ++pos) {                                \
               float v = ar[b][mt * 16 + g * 4 + pos];                        \
               ah[mt][pos] = f2tf32(v);                                       \
               al[mt][pos] = f2tf32(v - __uint_as_float(ah[mt][pos]));        \
           }                                                                  \
           _Pragma("unroll")                                                  \
           for (int nt = 0; nt < 8; ++nt) {                                   \
               uint32_t bq[4];                                                \
               uint32_t addr = sb + (s) * STAGE                               \
                   + (uint32_t)((nt * 8 + r) * 256                            \
                   + ((g * 64 + c * 16) ^ (r << 4)));                         \
               asm volatile("ld.shared.v4.b32 {%0,%1,%2,%3}, [%4];"           \
                   : "=r"(bq[0]), "=r"(bq[1]), "=r"(bq[2]), "=r"(bq[3])       \
                   : "r"(addr));                                              \
               _Pragma("unroll")                                              \
               for (int mt = 0; mt < 2; ++mt) {                               \
                   mma_tf32(acc[mt][nt], ah[mt], bq[0], bq[2]);               \
                   mma_tf32(acc[mt][nt], ah[mt], bq[1], bq[3]);               \
                   mma_tf32(acc[mt][nt], al[mt], bq[0], bq[2]);               \
               } } } }

    // -------- prologue --------
    LOAD_W(0);
    STS_W(0);
    LOAD_W(1);
    LOAD_A(0, 0);
    __syncthreads();

    // -------- main loop --------
    for (int kc = 0; kc < NCHUNK; ++kc) {
        const int s = kc & 1;
        if (kc + 1 < NCHUNK) {
            LOAD_A(kc + 1, s ^ 1);
            STS_W(s ^ 1);                 // wv holds chunk kc+1
        }
        if (kc + 2 < NCHUNK) LOAD_W(kc + 2);
        __syncthreads();                  // stage s^1 stores visible next iter
        COMPUTE(s, s);
        __syncthreads();                  // stage s reads done before overwrite
    }

    // -------- dump logits to smem (stride 65: conflict-free column scans) ----
    float* lg = (float*)smem;
#pragma unroll
    for (int mt = 0; mt < 2; ++mt)
#pragma unroll
        for (int nt = 0; nt < 8; ++nt) {
            int row = wid * 32 + mt * 16 + r;
            int col = nt * 8 + c * 2;
            lg[row * LG_STRIDE + col]           = acc[mt][nt][0];
            lg[row * LG_STRIDE + col + 1]       = acc[mt][nt][1];
            lg[(row + 8) * LG_STRIDE + col]     = acc[mt][nt][2];
            lg[(row + 8) * LG_STRIDE + col + 1] = acc[mt][nt][3];
        }
    __syncthreads();

    // -------- per-token epilogue: one thread per token (tid == local token) --
    const float* lrow = &lg[tid * LG_STRIDE];

    // top-4 scan ('>' keeps lower index first on ties, matching jax.lax.top_k)
    float m0 = -INFINITY, m1 = -INFINITY, m2 = -INFINITY, m3 = -INFINITY;
    int i0 = 0, i1 = 0, i2 = 0, i3 = 0;
#pragma unroll 8
    for (int e = 0; e < E_DIM; ++e) {
        float v = lrow[e];
        if (v > m0)      { m3=m2;i3=i2; m2=m1;i2=i1; m1=m0;i1=i0; m0=v;i0=e; }
        else if (v > m1) { m3=m2;i3=i2; m2=m1;i2=i1; m1=v;i1=e; }
        else if (v > m2) { m3=m2;i3=i2; m2=v;i2=e; }
        else if (v > m3) { m3=v;i3=e; }
    }

    // -------- fp64 fixup for near-ties (ordering becomes exact) -------------
    bool flag = (m0 - m1 < TAU) || (m1 - m2 < TAU) || (m2 - m3 < TAU);
    unsigned bal = __ballot_sync(0xFFFFFFFFu, flag);
    while (bal) {
        int src = __ffs(bal) - 1;
        bal &= bal - 1;
        int tt = t0 + (wid << 5) + src;
        int e4[4];
        e4[0] = __shfl_sync(0xFFFFFFFFu, i0, src);
        e4[1] = __shfl_sync(0xFFFFFFFFu, i1, src);
        e4[2] = __shfl_sync(0xFFFFFFFFu, i2, src);
        e4[3] = __shfl_sync(0xFFFFFFFFu, i3, src);
        double s4[4] = {0.0, 0.0, 0.0, 0.0};
        const float* xrow2 = x + (size_t)tt * D_DIM;
        for (int k = lane; k < D_DIM; k += 32) {
            double xv = (double)xrow2[k];
#pragma unroll
            for (int j = 0; j < 4; ++j)
                s4[j] += xv * (double)W[(size_t)e4[j] * D_DIM + k];
        }
#pragma unroll
        for (int off = 16; off > 0; off >>= 1)
#pragma unroll
            for (int j = 0; j < 4; ++j)
                s4[j] += __shfl_xor_sync(0xFFFFFFFFu, s4[j], off);
        if (lane == src) {
            // bubble-sort 4 descending by exact value (strict > keeps
            // earlier/lower-ranked first on exact ties)
            for (int a = 0; a < 3; ++a)
                for (int b = 0; b < 3 - a; ++b)
                    if (s4[b + 1] > s4[b]) {
                        double td = s4[b]; s4[b] = s4[b + 1]; s4[b + 1] = td;
                        int ti = e4[b]; e4[b] = e4[b + 1]; e4[b + 1] = ti;
                    }
            i0 = e4[0];
            i1 = e4[1];
        }
    }

    // -------- softmax + outputs --------
    {
        float ssum = 0.f;
#pragma unroll 8
        for (int e = 0; e < E_DIM; ++e) ssum += expf(lrow[e] - m0);
        const float inv  = 1.0f / ssum;
        const float p1   = expf(lrow[i0] - m0) * inv;
        const float p2   = expf(lrow[i1] - m0) * inv;
        const float rinv = 1.0f / (p1 + p2);

        const int t = t0 + tid;
        const size_t TT = (size_t)T;
        float* mask_o = out + (size_t)t * E_DIM;
        float* idx_o  = out + TT * E_DIM + (size_t)t * TOPK;
        float* rp_o   = out + TT * (E_DIM + TOPK) + (size_t)t * E_DIM;
        float* p_o    = out + TT * (2 * E_DIM + TOPK) + (size_t)t * E_DIM;

        idx_o[0] = (float)i0;
        idx_o[1] = (float)i1;

#pragma unroll 4
        for (int e = 0; e < E_DIM; e += 4) {
            float4 pv, mv, rv;
            float p;
            p = expf(lrow[e + 0] - m0) * inv;
            mv.x = (e + 0 == i0 || e + 0 == i1) ? 1.0f : 0.0f; pv.x = p; rv.x = mv.x * p * rinv;
            p = expf(lrow[e + 1] - m0) * inv;
            mv.y = (e + 1 == i0 || e + 1 == i1) ? 1.0f : 0.0f; pv.y = p; rv.y = mv.y * p * rinv;
            p = expf(lrow[e + 2] - m0) * inv;
            mv.z = (e + 2 == i0 || e + 2 == i1) ? 1.0f : 0.0f; pv.z = p; rv.z = mv.z * p * rinv;
            p = expf(lrow[e + 3] - m0) * inv;
            mv.w = (e + 3 == i0 || e + 3 == i1) ? 1.0f : 0.0f; pv.w = p; rv.w = mv.w * p * rinv;

            *(float4*)(mask_o + e) = mv;
            *(float4*)(p_o    + e) = pv;
            *(float4*)(rp_o   + e) = rv;
        }
    }
}

extern "C" void kernel_launch(void* const* d_in, const int* in_sizes, int n_in,
                              void* d_out, int out_size)
{
    const float* x = (const float*)d_in[0];
    const float* W = (const float*)d_in[1];
    float* out = (float*)d_out;

    const int T = in_sizes[0] / D_DIM;      // 16384
    const int grid = T / M_TILE;            // 128

    router_mma_kernel<<<grid, THREADS, SMEM_TOTAL>>>(x, W, out, T);
}